// round 16
// baseline (speedup 1.0000x reference)
#include <cuda_runtime.h>
#include <cuda_fp16.h>
#include <math.h>

#define N_USERS 50000
#define N_ENT   100000
#define CDIM    64
#define E_EDGES 1500000
#define NNZ_I   1000000
#define R1      15
#define R2      47
#define NF      4

// ---- output layout (flattened tuple) ----
#define OUT_E0   0
#define OUT_U0   6400000
#define OUT_COR0 9600000
#define OUT_E1   9600001
#define OUT_U1   16000001
#define OUT_COR1 19200001

// ---- scan decomposition ----
#define SCAN_TILE 1024
#define EBLK 98   // ceil(N_ENT / SCAN_TILE)
#define UBLK 49   // ceil(N_USERS / SCAN_TILE)

// ---- scratch (__device__ globals; accessed ONLY from device code) ----
// fp16 state packed per lane: float2 = {branchC half2, branchD half2}
__device__ float2  d_eCD[N_ENT * 32];
__device__ float2  d_uCD[N_USERS * 32];
__device__ __half2 d_ein16[N_ENT * 32];   // fp16 copy of entity_emb (it0 gathers)
__device__ int    d_cnt[N_ENT];
__device__ int    d_ucnt[N_USERS];
__device__ int    d_start[N_ENT + 1];
__device__ int    d_cursor[N_ENT];
__device__ int    d_ustart[N_USERS + 1];
__device__ int    d_ucursor[N_USERS];
__device__ int    d_bsum[EBLK + UBLK];    // raw per-tile sums (NOT scanned)
__device__ int    d_hist[512];            // degree buckets: ent [0,256), usr [256,512)
__device__ int    d_perm[N_ENT];          // entity ids, descending-degree grouped
__device__ int    d_uperm[N_USERS];       // user ids, descending-degree grouped
__device__ int    d_pack[E_EDGES];        // tail(17b) | wc(4b)<<17 | wd(6b)<<21
__device__ int2   d_unnz[NNZ_I];          // {col, val bits}
__device__ float  d_l_cur[2][NF * CDIM];
__device__ float  d_l_acc[2][NF * CDIM];
__device__ float  d_L1[2][NF * CDIM];
__device__ float  d_l_new[2][NF * CDIM];

// ================= utility =================
__device__ __forceinline__ float warp_sum(float v) {
#pragma unroll
    for (int o = 16; o; o >>= 1) v += __shfl_xor_sync(0xffffffffu, v, o);
    return v;
}

union CDPack {
    float2  f;
    __half2 h[2];
};

// descending-degree bucket: heavy vertices get low bucket ids
__device__ __forceinline__ int deg_bucket(int d) { return 255 - min(d, 255); }

// ====== setup: zero counts/hist, init latent, fp16 input staging ===========
__global__ void setup_kernel(float* __restrict__ cor0, float* __restrict__ cor1,
                             const float* __restrict__ l0, const float* __restrict__ l1,
                             const float2* __restrict__ ent2) {
    int stride = gridDim.x * blockDim.x;
    int gid = blockIdx.x * blockDim.x + threadIdx.x;
    for (int i = gid; i < N_ENT; i += stride) d_cnt[i] = 0;
    for (int i = gid; i < N_USERS; i += stride) d_ucnt[i] = 0;
    if (gid < 512) d_hist[gid] = 0;
    for (int i = gid; i < N_ENT * 32; i += stride) {
        float2 v = ent2[i];
        d_ein16[i] = __floats2half2_rn(v.x, v.y);
    }
    for (int i = gid; i < NF * CDIM; i += stride) {
        float a = l0[i], b = l1[i];
        d_l_cur[0][i] = a; d_l_acc[0][i] = a;
        d_l_cur[1][i] = b; d_l_acc[1][i] = b;
    }
    if (gid == 0) { *cor0 = 0.f; *cor1 = 0.f; }
}

// ================= degree counting =================
__global__ void cnt_all(const int* __restrict__ head, const int* __restrict__ rows) {
    int gid = blockIdx.x * blockDim.x + threadIdx.x;
    if (gid < E_EDGES) atomicAdd(&d_cnt[head[gid]], 1);
    if (gid < NNZ_I)   atomicAdd(&d_ucnt[rows[gid]], 1);
}

// ========== scan phase A: raw per-tile sums + degree histogram =============
__global__ void scan_phaseA() {
    int b = blockIdx.x;
    bool usr = (b >= EBLK);
    const int* cnt = usr ? d_ucnt : d_cnt;
    int n = usr ? N_USERS : N_ENT;
    int segh = usr ? 256 : 0;
    int base = (usr ? b - EBLK : b) * SCAN_TILE;
    int tid = threadIdx.x;  // 256
    __shared__ int sm[256];
    __shared__ int lh[256];
    lh[tid] = 0;
    __syncthreads();
    int s = 0;
#pragma unroll
    for (int k = 0; k < 4; k++) {
        int idx = base + tid + k * 256;
        if (idx < n) {
            int v = cnt[idx];
            s += v;
            atomicAdd(&lh[deg_bucket(v)], 1);
        }
    }
    sm[tid] = s;
    __syncthreads();
    for (int o = 128; o; o >>= 1) {
        if (tid < o) sm[tid] += sm[tid + o];
        __syncthreads();
    }
    if (tid == 0) d_bsum[b] = sm[0];
    if (lh[tid]) atomicAdd(&d_hist[segh + tid], lh[tid]);
}

// ========== scan the 2x256 degree-bucket histograms (exclusive) ============
__global__ void scan_hist() {
    int tid = threadIdx.x;
    if (tid < 2) {
        int base = tid * 256;
        int run = 0;
        for (int i = 0; i < 256; i++) {
            int v = d_hist[base + i];
            d_hist[base + i] = run;
            run += v;
        }
    }
}

// ==== scan phase C: base-offset reduce + per-tile rescan + perm scatter ====
__global__ void scan_phaseC() {
    int b = blockIdx.x;
    bool usr = (b >= EBLK);
    const int* cnt = usr ? d_ucnt : d_cnt;
    int* start  = usr ? d_ustart : d_start;
    int* cursor = usr ? d_ucursor : d_cursor;
    int* perm   = usr ? d_uperm : d_perm;
    int n = usr ? N_USERS : N_ENT;
    int lastb = usr ? (EBLK + UBLK - 1) : (EBLK - 1);
    int segs = usr ? EBLK : 0;
    int segh = usr ? 256 : 0;
    int base = (usr ? b - EBLK : b) * SCAN_TILE;
    int tid = threadIdx.x;  // 256
    __shared__ int sm[256];

    int p = 0;
    for (int j = segs + tid; j < b; j += 256) p += d_bsum[j];
    sm[tid] = p;
    __syncthreads();
    for (int o = 128; o; o >>= 1) {
        if (tid < o) sm[tid] += sm[tid + o];
        __syncthreads();
    }
    int base_off = sm[0];
    __syncthreads();

    int idx0 = base + tid * 4;
    int v[4]; int s = 0;
#pragma unroll
    for (int k = 0; k < 4; k++) {
        int idx = idx0 + k;
        v[k] = (idx < n) ? cnt[idx] : 0;
        s += v[k];
    }
    sm[tid] = s;
    __syncthreads();
    for (int o = 1; o < 256; o <<= 1) {
        int t = 0;
        if (tid >= o) t = sm[tid - o];
        __syncthreads();
        if (tid >= o) sm[tid] += t;
        __syncthreads();
    }
    int run = base_off + (tid ? sm[tid - 1] : 0);
#pragma unroll
    for (int k = 0; k < 4; k++) {
        int idx = idx0 + k;
        if (idx < n) {
            start[idx] = run; cursor[idx] = run;
            int pos = atomicAdd(&d_hist[segh + deg_bucket(v[k])], 1);
            perm[pos] = idx;
        }
        run += v[k];
    }
    if (b == lastb && tid == 255) start[n] = run;
}

// ================= CSR fill (both graphs, one launch) ======================
__global__ void fill_all(const int* __restrict__ head, const int* __restrict__ tail,
                         const int* __restrict__ etype, const int* __restrict__ cate,
                         const int* __restrict__ rows, const int* __restrict__ cols,
                         const float* __restrict__ vals) {
    int gid = blockIdx.x * blockDim.x + threadIdx.x;
    if (gid < E_EDGES) {
        int h = head[gid], t = tail[gid];
        int wc = etype[gid] - 1;
        int wd = cate[t] - 1;
        int pos = atomicAdd(&d_cursor[h], 1);
        d_pack[pos] = t | (wc << 17) | (wd << 21);
    }
    if (gid < NNZ_I) {
        int r = rows[gid];
        int pos = atomicAdd(&d_ucursor[r], 1);
        d_unnz[pos] = make_int2(cols[gid], __float_as_int(vals[gid]));
    }
}

// ====== dense (latent/score) for BOTH branches (grid=2) + latent_post ======
__global__ void dense_both(
    const float* __restrict__ cW1, const float* __restrict__ cb1,
    const float* __restrict__ cW2, const float* __restrict__ cb2,
    const float* __restrict__ cWwa, const float* __restrict__ cbwa,
    const float* __restrict__ wC,
    const float* __restrict__ eW1, const float* __restrict__ eb1,
    const float* __restrict__ eW2, const float* __restrict__ eb2,
    const float* __restrict__ eWwa, const float* __restrict__ ebwa,
    const float* __restrict__ wD,
    int it, int is_last) {
    __shared__ float sL[NF * CDIM];
    __shared__ float sLW2[NF * CDIM];
    __shared__ float sWW2[R2 * CDIM];
    __shared__ float srp[NF * R2];
    __shared__ float sact[NF * R2];
    __shared__ float wsum[8];
    int b = blockIdx.x;
    int R = b ? R2 : R1;
    const float* W1   = (b ? eW1 : cW1) + it * CDIM * CDIM;
    const float* b1   = (b ? eb1 : cb1) + it * CDIM;
    const float* W2   = (b ? eW2 : cW2) + it * CDIM * CDIM;
    const float* b2   = (b ? eb2 : cb2) + it * CDIM;
    const float* Wwa  = (b ? eWwa : cWwa) + it * R * R;
    const float* bwa  = (b ? ebwa : cbwa) + it * R;
    const float* wtab = b ? wD : wC;
    int tid = threadIdx.x;  // 256 threads

    if (tid < NF * CDIM) sL[tid] = d_l_cur[b][tid];
    __syncthreads();

    {
        int f = tid >> 6, j = tid & 63;
        float s1 = b1[j], s2 = b2[j];
#pragma unroll 8
        for (int k = 0; k < CDIM; k++) {
            float lv = sL[f * CDIM + k];
            s1 = fmaf(lv, W1[k * CDIM + j], s1);
            s2 = fmaf(lv, W2[k * CDIM + j], s2);
        }
        d_L1[b][tid] = s1;
        sLW2[tid] = s2;
    }
    for (int o = tid; o < R * CDIM; o += 256) {
        int r = o >> 6, j = o & 63;
        float s = b2[j];
#pragma unroll 8
        for (int k = 0; k < CDIM; k++) s = fmaf(wtab[r * CDIM + k], W2[k * CDIM + j], s);
        sWW2[o] = s;
    }
    __syncthreads();

    for (int o = tid; o < NF * R; o += 256) {
        int f = o / R, r = o % R;
        float s = 0.f;
#pragma unroll 8
        for (int jx = 0; jx < CDIM; jx++) s = fmaf(sLW2[f * CDIM + jx], sWW2[r * CDIM + jx], s);
        srp[o] = s;
    }
    __syncthreads();

    for (int o = tid; o < NF * R; o += 256) {
        int f = o / R, r2 = o % R;
        float s = bwa[r2];
        for (int r = 0; r < R; r++) s = fmaf(srp[f * R + r], Wwa[r * R + r2], s);
        sact[o] = (s >= 0.f) ? s : 0.2f * s;
    }
    __syncthreads();

    if (tid < NF) {
        float m = -1e30f;
        for (int r = 0; r < R; r++) m = fmaxf(m, sact[tid * R + r]);
        float sum = 0.f;
        for (int r = 0; r < R; r++) { float ev = expf(sact[tid * R + r] - m); sact[tid * R + r] = ev; sum += ev; }
        float inv = 1.f / sum;
        for (int r = 0; r < R; r++) sact[tid * R + r] *= inv;
    }
    __syncthreads();

    float lnew;
    {
        int f = tid >> 6, j = tid & 63;
        float s = 0.f;
        for (int r = 0; r < R; r++) s = fmaf(sact[f * R + r], wtab[r * CDIM + j], s);
        d_l_new[b][tid] = s;
        lnew = s;
    }

    // ---- fused latent_post epilogue ----
    float ps = warp_sum(lnew * lnew);
    if ((tid & 31) == 0) wsum[tid >> 5] = ps;
    __syncthreads();
    int f = tid >> 6;
    float nrm = sqrtf(wsum[2 * f] + wsum[2 * f + 1]);
    float inv = 1.f / fmaxf(nrm, 1e-12f);
    float n = lnew * inv;
    if (b == 1) {
        d_l_cur[1][tid] = n;
        d_l_acc[1][tid] += n;
    } else {
        d_l_cur[0][tid] = lnew;
        if (is_last) d_l_acc[0][tid] = n + lnew;
    }
}

// ============ entity pass: it0 dual (perm-scheduled) ========================
__global__ __launch_bounds__(256) void ent_pass_dual(
    const float* __restrict__ wC, const float* __restrict__ wD,
    const float* __restrict__ ent_emb,
    float* __restrict__ outC, float* __restrict__ outD) {
    __shared__ float2 swC[R1 * 32];
    __shared__ float2 swD[R2 * 32];
    int tid = threadIdx.x;
    for (int o = tid; o < R1 * 32; o += 256) swC[o] = ((const float2*)wC)[o];
    for (int o = tid; o < R2 * 32; o += 256) swD[o] = ((const float2*)wD)[o];
    __syncthreads();
    int warp = tid >> 5, lane = tid & 31;
    int hv = blockIdx.x * 8 + warp;
    if (hv >= N_ENT) return;
    int h = __ldg(&d_perm[hv]);
    int s = d_start[h], e = d_start[h + 1];
    float cx = 0.f, cy = 0.f, dx = 0.f, dy = 0.f;
#pragma unroll 4
    for (int k = s; k < e; k++) {
        int p = __ldg(&d_pack[k]);
        int t = p & 0x1FFFF;
        float2 ev = __half22float2(d_ein16[t * 32 + lane]);
        float2 wc = swC[((p >> 17) & 15) * 32 + lane];
        float2 wd = swD[((p >> 21) & 63) * 32 + lane];
        cx = fmaf(ev.x, wc.x, cx); cy = fmaf(ev.y, wc.y, cy);
        dx = fmaf(ev.x, wd.x, dx); dy = fmaf(ev.y, wd.y, dy);
    }
    float ic = 1.f / fmaxf((float)(e - s), 1.f);
    cx *= ic; cy *= ic; dx *= ic; dy *= ic;
    float sC = warp_sum(cx * cx + cy * cy);
    float sD = warp_sum(dx * dx + dy * dy);
    float iC = 1.f / fmaxf(sqrtf(sC), 1e-12f);
    float iD = 1.f / fmaxf(sqrtf(sD), 1e-12f);
    cx *= iC; cy *= iC; dx *= iD; dy *= iD;
    CDPack pk;
    pk.h[0] = __floats2half2_rn(cx, cy);
    pk.h[1] = __floats2half2_rn(dx, dy);
    d_eCD[h * 32 + lane] = pk.f;
    float2 e2 = ((const float2*)ent_emb)[h * 32 + lane];
    ((float2*)outC)[h * 32 + lane] = make_float2(e2.x + cx, e2.y + cy);
    outD[h * 64 + 2 * lane]     = e2.x + dx;
    outD[h * 64 + 2 * lane + 1] = e2.y + dy;
}

// ====== entity pass: it1 both branches fused (perm-scheduled) ==============
__global__ __launch_bounds__(256) void ent_pass_final(
    const float* __restrict__ wC, const float* __restrict__ wD,
    float* __restrict__ outC, float* __restrict__ outD) {
    __shared__ float2 swC[R1 * 32];
    __shared__ float2 swD[R2 * 32];
    int tid = threadIdx.x;
    for (int o = tid; o < R1 * 32; o += 256) swC[o] = ((const float2*)wC)[o];
    for (int o = tid; o < R2 * 32; o += 256) swD[o] = ((const float2*)wD)[o];
    __syncthreads();
    int warp = tid >> 5, lane = tid & 31;
    int hv = blockIdx.x * 8 + warp;
    if (hv >= N_ENT) return;
    int h = __ldg(&d_perm[hv]);
    int s = d_start[h], e = d_start[h + 1];
    float cx = 0.f, cy = 0.f, dx = 0.f, dy = 0.f;
#pragma unroll 4
    for (int k = s; k < e; k++) {
        int p = __ldg(&d_pack[k]);
        int t = p & 0x1FFFF;
        CDPack pk;
        pk.f = __ldg(&d_eCD[t * 32 + lane]);
        float2 evC = __half22float2(pk.h[0]);
        float2 evD = __half22float2(pk.h[1]);
        float2 wc = swC[((p >> 17) & 15) * 32 + lane];
        float2 wd = swD[((p >> 21) & 63) * 32 + lane];
        cx = fmaf(evC.x, wc.x, cx); cy = fmaf(evC.y, wc.y, cy);
        dx = fmaf(evD.x, wd.x, dx); dy = fmaf(evD.y, wd.y, dy);
    }
    float ic = 1.f / fmaxf((float)(e - s), 1.f);
    cx *= ic; cy *= ic; dx *= ic; dy *= ic;
    float sC = warp_sum(cx * cx + cy * cy);
    float sD = warp_sum(dx * dx + dy * dy);
    float iC = 1.f / fmaxf(sqrtf(sC), 1e-12f);
    float iD = 1.f / fmaxf(sqrtf(sD), 1e-12f);
    cx *= iC; cy *= iC; dx *= iD; dy *= iD;
    float2 o2 = ((const float2*)outC)[h * 32 + lane];
    ((float2*)outC)[h * 32 + lane] = make_float2(o2.x + cx, o2.y + cy);
    outD[h * 64 + 2 * lane]     += dx;
    outD[h * 64 + 2 * lane + 1] += dy;
}

// ================= user score/mix epilogues =================================
struct UsrShared {
    float W1[4096];
    float b1[64], L1[256], LN[256], Wua[16], bua[4];
    float Row[8][64];
};

__device__ __forceinline__ void usr_epi_core(
    const UsrShared& sh, int lane, float a0, float a1,
    float ax, float ay, float& rx, float& ry) {
    float sc0 = warp_sum(a0 * sh.L1[lane] + a1 * sh.L1[lane + 32]);
    float sc1 = warp_sum(a0 * sh.L1[64 + lane] + a1 * sh.L1[64 + lane + 32]);
    float sc2 = warp_sum(a0 * sh.L1[128 + lane] + a1 * sh.L1[128 + lane + 32]);
    float sc3 = warp_sum(a0 * sh.L1[192 + lane] + a1 * sh.L1[192 + lane + 32]);
    float t[4]; float m = -1e30f;
#pragma unroll
    for (int g = 0; g < 4; g++) {
        float sv = sh.bua[g] + sc0 * sh.Wua[g] + sc1 * sh.Wua[4 + g]
                 + sc2 * sh.Wua[8 + g] + sc3 * sh.Wua[12 + g];
        sv = (sv >= 0.f) ? sv : 0.2f * sv;
        t[g] = sv; m = fmaxf(m, sv);
    }
    float es = 0.f;
#pragma unroll
    for (int g = 0; g < 4; g++) { t[g] = expf(t[g] - m); es += t[g]; }
    float ies = 1.f / es;
    float mixx = 0.f, mixy = 0.f;
#pragma unroll
    for (int g = 0; g < 4; g++) {
        float sg = t[g] * ies;
        mixx = fmaf(sg, sh.LN[g * 64 + 2 * lane], mixx);
        mixy = fmaf(sg, sh.LN[g * 64 + 2 * lane + 1], mixy);
    }
    rx = ax * (1.f + mixx); ry = ay * (1.f + mixy);
    float ss = warp_sum(rx * rx + ry * ry);
    float inv = 1.f / fmaxf(sqrtf(ss), 1e-12f);
    rx *= inv; ry *= inv;
}

__device__ __forceinline__ void usr_epilogue(
    UsrShared& sh, int warp, int lane, float u0, float u1,
    float ax, float ay, float& rx, float& ry) {
    sh.Row[warp][2 * lane] = u0; sh.Row[warp][2 * lane + 1] = u1;
    __syncwarp();
    float a0 = sh.b1[lane], a1 = sh.b1[lane + 32];
#pragma unroll 16
    for (int k = 0; k < 64; k++) {
        float uk = sh.Row[warp][k];
        a0 = fmaf(uk, sh.W1[k * 64 + lane], a0);
        a1 = fmaf(uk, sh.W1[k * 64 + lane + 32], a1);
    }
    usr_epi_core(sh, lane, a0, a1, ax, ay, rx, ry);
    __syncwarp();
}

__device__ __forceinline__ void usr_load_shared(
    UsrShared& sh, int tid, int b,
    const float* W1, const float* b1, const float* Wua, const float* bua) {
    for (int o = tid; o < 4096; o += 256) sh.W1[o] = W1[o];
    if (tid < 64) sh.b1[tid] = b1[tid];
    if (tid < 256) { sh.L1[tid] = d_L1[b][tid]; sh.LN[tid] = d_l_new[b][tid]; }
    if (tid < 16) sh.Wua[tid] = Wua[tid];
    if (tid < 4) sh.bua[tid] = bua[tid];
}

// ====== user pass: it0 dual (perm-scheduled, merged dual epilogue) =========
__global__ __launch_bounds__(256) void usr_pass_dual(
    const float* __restrict__ u_emb,
    const float* __restrict__ W1a, const float* __restrict__ b1a,
    const float* __restrict__ Wua_a, const float* __restrict__ bua_a,
    const float* __restrict__ W1b, const float* __restrict__ b1b,
    const float* __restrict__ Wua_b, const float* __restrict__ bua_b,
    float* __restrict__ outA, float* __restrict__ outB) {
    __shared__ UsrShared shA;
    __shared__ UsrShared shB;
    int tid = threadIdx.x;
    usr_load_shared(shA, tid, 0, W1a, b1a, Wua_a, bua_a);
    usr_load_shared(shB, tid, 1, W1b, b1b, Wua_b, bua_b);
    __syncthreads();
    int warp = tid >> 5, lane = tid & 31;
    int uv = blockIdx.x * 8 + warp;
    if (uv >= N_USERS) return;
    int u = __ldg(&d_uperm[uv]);
    int s = d_ustart[u], e = d_ustart[u + 1];
    float ax = 0.f, ay = 0.f;
#pragma unroll 4
    for (int k = s; k < e; k++) {
        int2 nz = __ldg(&d_unnz[k]);
        float v = __int_as_float(nz.y);
        float2 ev = __half22float2(d_ein16[nz.x * 32 + lane]);
        ax = fmaf(ev.x, v, ax); ay = fmaf(ev.y, v, ay);
    }
    float2 u2 = ((const float2*)u_emb)[u * 32 + lane];
    shA.Row[warp][2 * lane] = u2.x; shA.Row[warp][2 * lane + 1] = u2.y;
    __syncwarp();
    float a0A = shA.b1[lane], a1A = shA.b1[lane + 32];
    float a0B = shB.b1[lane], a1B = shB.b1[lane + 32];
#pragma unroll 16
    for (int k = 0; k < 64; k++) {
        float uk = shA.Row[warp][k];
        a0A = fmaf(uk, shA.W1[k * 64 + lane], a0A);
        a1A = fmaf(uk, shA.W1[k * 64 + lane + 32], a1A);
        a0B = fmaf(uk, shB.W1[k * 64 + lane], a0B);
        a1B = fmaf(uk, shB.W1[k * 64 + lane + 32], a1B);
    }
    float rxA, ryA, rxB, ryB;
    usr_epi_core(shA, lane, a0A, a1A, ax, ay, rxA, ryA);
    usr_epi_core(shB, lane, a0B, a1B, ax, ay, rxB, ryB);
    CDPack pk;
    pk.h[0] = __floats2half2_rn(rxA, ryA);
    pk.h[1] = __floats2half2_rn(rxB, ryB);
    d_uCD[u * 32 + lane] = pk.f;
    ((float2*)outA)[u * 32 + lane] = make_float2(u2.x + rxA, u2.y + ryA);
    outB[u * 64 + 2 * lane]     = u2.x + rxB;
    outB[u * 64 + 2 * lane + 1] = u2.y + ryB;
}

// ====== user pass: it1 both branches fused (perm-scheduled) ================
__global__ __launch_bounds__(256) void usr_pass_final(
    const float* __restrict__ W1a, const float* __restrict__ b1a,
    const float* __restrict__ Wua_a, const float* __restrict__ bua_a,
    const float* __restrict__ W1b, const float* __restrict__ b1b,
    const float* __restrict__ Wua_b, const float* __restrict__ bua_b,
    float* __restrict__ outA, float* __restrict__ outB) {
    __shared__ UsrShared shA;
    __shared__ UsrShared shB;
    int tid = threadIdx.x;
    usr_load_shared(shA, tid, 0, W1a, b1a, Wua_a, bua_a);
    usr_load_shared(shB, tid, 1, W1b, b1b, Wua_b, bua_b);
    __syncthreads();
    int warp = tid >> 5, lane = tid & 31;
    int uv = blockIdx.x * 8 + warp;
    if (uv >= N_USERS) return;
    int u = __ldg(&d_uperm[uv]);
    int s = d_ustart[u], e = d_ustart[u + 1];
    float axA = 0.f, ayA = 0.f, axB = 0.f, ayB = 0.f;
#pragma unroll 4
    for (int k = s; k < e; k++) {
        int2 nz = __ldg(&d_unnz[k]);
        float v = __int_as_float(nz.y);
        CDPack pk;
        pk.f = __ldg(&d_eCD[nz.x * 32 + lane]);
        float2 evA = __half22float2(pk.h[0]);
        float2 evB = __half22float2(pk.h[1]);
        axA = fmaf(evA.x, v, axA); ayA = fmaf(evA.y, v, ayA);
        axB = fmaf(evB.x, v, axB); ayB = fmaf(evB.y, v, ayB);
    }
    CDPack ur;
    ur.f = d_uCD[u * 32 + lane];
    float rx, ry;
    {
        float2 uu = __half22float2(ur.h[0]);
        usr_epilogue(shA, warp, lane, uu.x, uu.y, axA, ayA, rx, ry);
        float2 o2 = ((const float2*)outA)[u * 32 + lane];
        ((float2*)outA)[u * 32 + lane] = make_float2(o2.x + rx, o2.y + ry);
    }
    {
        float2 uu = __half22float2(ur.h[1]);
        usr_epilogue(shB, warp, lane, uu.x, uu.y, axB, ayB, rx, ry);
        outB[u * 64 + 2 * lane]     += rx;
        outB[u * 64 + 2 * lane + 1] += ry;
    }
}

// ========= distance-correlation: 12 blocks (6 pairs x 2 branches) ==========
__global__ void cor_kernel(float* __restrict__ out0, float* __restrict__ out1) {
    __shared__ float t1[64], t2[64];
    __shared__ float Ma[4096], Mb[4096];
    __shared__ float cmA[64], rmA[64], cmB[64], rmB[64];
    __shared__ float gA, gB;
    __shared__ float r0[256], r1[256], r2[256];
    int tid = threadIdx.x;
    const int PI[6] = {0, 0, 0, 1, 1, 2};
    const int PJ[6] = {1, 2, 3, 2, 3, 3};
    int b = blockIdx.x / 6;
    int pr = blockIdx.x % 6;
    float* out = b ? out1 : out0;
    int i = PI[pr], j = PJ[pr];
    if (tid < 64) { t1[tid] = d_l_acc[b][i * 64 + tid]; t2[tid] = d_l_acc[b][j * 64 + tid]; }
    __syncthreads();
    for (int o = tid; o < 4096; o += 256) {
        int p = o >> 6, q = o & 63;
        float va = t1[p] * t1[p] - 2.f * t1[p] * t1[q] + t1[q] * t1[q];
        float vb = t2[p] * t2[p] - 2.f * t2[p] * t2[q] + t2[q] * t2[q];
        Ma[o] = sqrtf(fmaxf(va, 0.f) + 1e-8f);
        Mb[o] = sqrtf(fmaxf(vb, 0.f) + 1e-8f);
    }
    __syncthreads();
    if (tid < 64) {
        float s = 0.f;
        for (int p = 0; p < 64; p++) s += Ma[p * 64 + tid];
        cmA[tid] = s * (1.f / 64.f);
    } else if (tid < 128) {
        int p = tid - 64; float s = 0.f;
        for (int q = 0; q < 64; q++) s += Ma[p * 64 + q];
        rmA[p] = s * (1.f / 64.f);
    } else if (tid < 192) {
        int q = tid - 128; float s = 0.f;
        for (int p = 0; p < 64; p++) s += Mb[p * 64 + q];
        cmB[q] = s * (1.f / 64.f);
    } else {
        int p = tid - 192; float s = 0.f;
        for (int q = 0; q < 64; q++) s += Mb[p * 64 + q];
        rmB[p] = s * (1.f / 64.f);
    }
    __syncthreads();
    if (tid == 0) { float s = 0.f; for (int q = 0; q < 64; q++) s += cmA[q]; gA = s * (1.f / 64.f); }
    if (tid == 1) { float s = 0.f; for (int q = 0; q < 64; q++) s += cmB[q]; gB = s * (1.f / 64.f); }
    __syncthreads();
    float ab = 0.f, aa = 0.f, bb = 0.f;
    for (int o = tid; o < 4096; o += 256) {
        int p = o >> 6, q = o & 63;
        float Ac = Ma[o] - cmA[q] - rmA[p] + gA;
        float Bc = Mb[o] - cmB[q] - rmB[p] + gB;
        ab = fmaf(Ac, Bc, ab); aa = fmaf(Ac, Ac, aa); bb = fmaf(Bc, Bc, bb);
    }
    r0[tid] = ab; r1[tid] = aa; r2[tid] = bb;
    __syncthreads();
    for (int s = 128; s; s >>= 1) {
        if (tid < s) { r0[tid] += r0[tid + s]; r1[tid] += r1[tid + s]; r2[tid] += r2[tid + s]; }
        __syncthreads();
    }
    if (tid == 0) {
        const float n2 = 4096.f;
        float dab = sqrtf(fmaxf(r0[0] / n2, 0.f) + 1e-8f);
        float daa = sqrtf(fmaxf(r1[0] / n2, 0.f) + 1e-8f);
        float dbb = sqrtf(fmaxf(r2[0] / n2, 0.f) + 1e-8f);
        atomicAdd(out, dab / sqrtf(daa * dbb + 1e-8f));
    }
}

// ================= host =================
extern "C" void kernel_launch(void* const* d_in, const int* in_sizes, int n_in,
                              void* d_out, int out_size) {
    const float* user_emb       = (const float*)d_in[0];
    const float* entity_emb     = (const float*)d_in[1];
    const float* latent_emb     = (const float*)d_in[2];
    const float* latent_div_emb = (const float*)d_in[3];
    const float* weight         = (const float*)d_in[4];
    const float* weight_d       = (const float*)d_in[5];
    const float* cW1  = (const float*)d_in[6];
    const float* cb1  = (const float*)d_in[7];
    const float* cW2  = (const float*)d_in[8];
    const float* cb2  = (const float*)d_in[9];
    const float* cWua = (const float*)d_in[10];
    const float* cbua = (const float*)d_in[11];
    const float* cWwa = (const float*)d_in[12];
    const float* cbwa = (const float*)d_in[13];
    const float* eW1  = (const float*)d_in[14];
    const float* eb1  = (const float*)d_in[15];
    const float* eW2  = (const float*)d_in[16];
    const float* eb2  = (const float*)d_in[17];
    const float* eWua = (const float*)d_in[18];
    const float* ebua = (const float*)d_in[19];
    const float* eWwa = (const float*)d_in[20];
    const float* ebwa = (const float*)d_in[21];
    const float* interact_vals = (const float*)d_in[22];
    const int*   edge_index    = (const int*)d_in[23];
    const int*   edge_type     = (const int*)d_in[24];
    const int*   cate          = (const int*)d_in[25];
    const int*   irows         = (const int*)d_in[26];
    const int*   icols         = (const int*)d_in[27];

    const int* head = edge_index;
    const int* tail = edge_index + E_EDGES;
    float* out = (float*)d_out;

    const int ENT_BLOCKS = (N_ENT + 7) / 8;     // 12500
    const int USR_BLOCKS = (N_USERS + 7) / 8;   // 6250

    // ---- CSR build + degree-sorted scheduling permutations ----
    setup_kernel<<<512, 256>>>(out + OUT_COR0, out + OUT_COR1,
                               latent_emb, latent_div_emb,
                               (const float2*)entity_emb);
    cnt_all<<<(E_EDGES + 255) / 256, 256>>>(head, irows);
    scan_phaseA<<<EBLK + UBLK, 256>>>();
    scan_hist<<<1, 32>>>();
    scan_phaseC<<<EBLK + UBLK, 256>>>();
    fill_all<<<(E_EDGES + 255) / 256, 256>>>(head, tail, edge_type, cate,
                                             irows, icols, interact_vals);

    // ---- iteration 0 (both branches fused; fp16 staged input) ----
    dense_both<<<2, 256>>>(cW1, cb1, cW2, cb2, cWwa, cbwa, weight,
                           eW1, eb1, eW2, eb2, eWwa, ebwa, weight_d, 0, 0);
    ent_pass_dual<<<ENT_BLOCKS, 256>>>(weight, weight_d, entity_emb,
                                       out + OUT_E0, out + OUT_E1);
    usr_pass_dual<<<USR_BLOCKS, 256>>>(user_emb,
                                       cW1, cb1, cWua, cbua,
                                       eW1, eb1, eWua, ebua,
                                       out + OUT_U0, out + OUT_U1);

    // ---- iteration 1 (both branches fused; out += only; fp16 state) ----
    dense_both<<<2, 256>>>(cW1, cb1, cW2, cb2, cWwa, cbwa, weight,
                           eW1, eb1, eW2, eb2, eWwa, ebwa, weight_d, 1, 1);
    ent_pass_final<<<ENT_BLOCKS, 256>>>(weight, weight_d, out + OUT_E0, out + OUT_E1);
    usr_pass_final<<<USR_BLOCKS, 256>>>(cW1 + 4096, cb1 + 64, cWua + 16, cbua + 4,
                                        eW1 + 4096, eb1 + 64, eWua + 16, ebua + 4,
                                        out + OUT_U0, out + OUT_U1);

    // ---- distance correlations (both branches, one launch) ----
    cor_kernel<<<12, 256>>>(out + OUT_COR0, out + OUT_COR1);
}

// round 17
// speedup vs baseline: 1.0398x; 1.0398x over previous
#include <cuda_runtime.h>
#include <cuda_fp16.h>
#include <math.h>

#define N_USERS 50000
#define N_ENT   100000
#define CDIM    64
#define E_EDGES 1500000
#define NNZ_I   1000000
#define R1      15
#define R2      47
#define NF      4

// ---- output layout (flattened tuple) ----
#define OUT_E0   0
#define OUT_U0   6400000
#define OUT_COR0 9600000
#define OUT_E1   9600001
#define OUT_U1   16000001
#define OUT_COR1 19200001

// ---- scan decomposition ----
#define SCAN_TILE 1024
#define EBLK 98   // ceil(N_ENT / SCAN_TILE)
#define UBLK 49   // ceil(N_USERS / SCAN_TILE)

// ---- scratch (__device__ globals; accessed ONLY from device code) ----
// fp16 state packed per lane: float2 = {branchC half2, branchD half2}
__device__ float2  d_eCD[N_ENT * 32];
__device__ float2  d_uCD[N_USERS * 32];
__device__ __half2 d_ein16[N_ENT * 32];   // fp16 copy of entity_emb (it0 gathers)
__device__ int    d_cnt[N_ENT];
__device__ int    d_ucnt[N_USERS];
__device__ int    d_start[N_ENT + 1];
__device__ int    d_cursor[N_ENT];
__device__ int    d_ustart[N_USERS + 1];
__device__ int    d_ucursor[N_USERS];
__device__ int    d_bsum[EBLK + UBLK];    // raw per-tile sums (NOT scanned)
__device__ int    d_pack[E_EDGES];        // tail(17b) | wc(4b)<<17 | wd(6b)<<21
__device__ int2   d_unnz[NNZ_I];          // {col, val bits}
__device__ float  d_l_cur[2][NF * CDIM];
__device__ float  d_l_acc[2][NF * CDIM];
__device__ float  d_L1[2][NF * CDIM];
__device__ float  d_l_new[2][NF * CDIM];

// ================= utility =================
__device__ __forceinline__ float warp_sum(float v) {
#pragma unroll
    for (int o = 16; o; o >>= 1) v += __shfl_xor_sync(0xffffffffu, v, o);
    return v;
}

union CDPack {
    float2  f;
    __half2 h[2];
};

// ====== setup: zero counts, init latent, fp16 input staging, zero cor ======
__global__ void setup_kernel(float* __restrict__ cor0, float* __restrict__ cor1,
                             const float* __restrict__ l0, const float* __restrict__ l1,
                             const float2* __restrict__ ent2) {
    int stride = gridDim.x * blockDim.x;
    int gid = blockIdx.x * blockDim.x + threadIdx.x;
    for (int i = gid; i < N_ENT; i += stride) d_cnt[i] = 0;
    for (int i = gid; i < N_USERS; i += stride) d_ucnt[i] = 0;
    for (int i = gid; i < N_ENT * 32; i += stride) {
        float2 v = ent2[i];
        d_ein16[i] = __floats2half2_rn(v.x, v.y);
    }
    for (int i = gid; i < NF * CDIM; i += stride) {
        float a = l0[i], b = l1[i];
        d_l_cur[0][i] = a; d_l_acc[0][i] = a;
        d_l_cur[1][i] = b; d_l_acc[1][i] = b;
    }
    if (gid == 0) { *cor0 = 0.f; *cor1 = 0.f; }
}

// ================= degree counting =================
__global__ void cnt_all(const int* __restrict__ head, const int* __restrict__ rows) {
    int gid = blockIdx.x * blockDim.x + threadIdx.x;
    if (gid < E_EDGES) atomicAdd(&d_cnt[head[gid]], 1);
    if (gid < NNZ_I)   atomicAdd(&d_ucnt[rows[gid]], 1);
}

// ================= scan phase A: raw per-tile sums =========================
__global__ void scan_phaseA() {
    int b = blockIdx.x;
    bool usr = (b >= EBLK);
    const int* cnt = usr ? d_ucnt : d_cnt;
    int n = usr ? N_USERS : N_ENT;
    int base = (usr ? b - EBLK : b) * SCAN_TILE;
    int tid = threadIdx.x;  // 256
    int s = 0;
#pragma unroll
    for (int k = 0; k < 4; k++) {
        int idx = base + tid + k * 256;
        if (idx < n) s += cnt[idx];
    }
    __shared__ int sm[256];
    sm[tid] = s;
    __syncthreads();
    for (int o = 128; o; o >>= 1) {
        if (tid < o) sm[tid] += sm[tid + o];
        __syncthreads();
    }
    if (tid == 0) d_bsum[b] = sm[0];
}

// ==== scan phase C: in-block base-offset reduce + per-tile rescan ==========
__global__ void scan_phaseC() {
    int b = blockIdx.x;
    bool usr = (b >= EBLK);
    const int* cnt = usr ? d_ucnt : d_cnt;
    int* start  = usr ? d_ustart : d_start;
    int* cursor = usr ? d_ucursor : d_cursor;
    int n = usr ? N_USERS : N_ENT;
    int lastb = usr ? (EBLK + UBLK - 1) : (EBLK - 1);
    int segs = usr ? EBLK : 0;
    int base = (usr ? b - EBLK : b) * SCAN_TILE;
    int tid = threadIdx.x;  // 256
    __shared__ int sm[256];

    int p = 0;
    for (int j = segs + tid; j < b; j += 256) p += d_bsum[j];
    sm[tid] = p;
    __syncthreads();
    for (int o = 128; o; o >>= 1) {
        if (tid < o) sm[tid] += sm[tid + o];
        __syncthreads();
    }
    int base_off = sm[0];
    __syncthreads();

    int idx0 = base + tid * 4;
    int v[4]; int s = 0;
#pragma unroll
    for (int k = 0; k < 4; k++) {
        int idx = idx0 + k;
        v[k] = (idx < n) ? cnt[idx] : 0;
        s += v[k];
    }
    sm[tid] = s;
    __syncthreads();
    for (int o = 1; o < 256; o <<= 1) {
        int t = 0;
        if (tid >= o) t = sm[tid - o];
        __syncthreads();
        if (tid >= o) sm[tid] += t;
        __syncthreads();
    }
    int run = base_off + (tid ? sm[tid - 1] : 0);
#pragma unroll
    for (int k = 0; k < 4; k++) {
        int idx = idx0 + k;
        if (idx < n) { start[idx] = run; cursor[idx] = run; }
        run += v[k];
    }
    if (b == lastb && tid == 255) start[n] = run;
}

// ================= CSR fill (both graphs, one launch) ======================
__global__ void fill_all(const int* __restrict__ head, const int* __restrict__ tail,
                         const int* __restrict__ etype, const int* __restrict__ cate,
                         const int* __restrict__ rows, const int* __restrict__ cols,
                         const float* __restrict__ vals) {
    int gid = blockIdx.x * blockDim.x + threadIdx.x;
    if (gid < E_EDGES) {
        int h = head[gid], t = tail[gid];
        int wc = etype[gid] - 1;
        int wd = cate[t] - 1;
        int pos = atomicAdd(&d_cursor[h], 1);
        d_pack[pos] = t | (wc << 17) | (wd << 21);
    }
    if (gid < NNZ_I) {
        int r = rows[gid];
        int pos = atomicAdd(&d_ucursor[r], 1);
        d_unnz[pos] = make_int2(cols[gid], __float_as_int(vals[gid]));
    }
}

// ====== dense (latent/score) for BOTH branches (grid=2) + latent_post ======
__global__ void dense_both(
    const float* __restrict__ cW1, const float* __restrict__ cb1,
    const float* __restrict__ cW2, const float* __restrict__ cb2,
    const float* __restrict__ cWwa, const float* __restrict__ cbwa,
    const float* __restrict__ wC,
    const float* __restrict__ eW1, const float* __restrict__ eb1,
    const float* __restrict__ eW2, const float* __restrict__ eb2,
    const float* __restrict__ eWwa, const float* __restrict__ ebwa,
    const float* __restrict__ wD,
    int it, int is_last) {
    __shared__ float sL[NF * CDIM];
    __shared__ float sLW2[NF * CDIM];
    __shared__ float sWW2[R2 * CDIM];
    __shared__ float srp[NF * R2];
    __shared__ float sact[NF * R2];
    __shared__ float wsum[8];
    int b = blockIdx.x;
    int R = b ? R2 : R1;
    const float* W1   = (b ? eW1 : cW1) + it * CDIM * CDIM;
    const float* b1   = (b ? eb1 : cb1) + it * CDIM;
    const float* W2   = (b ? eW2 : cW2) + it * CDIM * CDIM;
    const float* b2   = (b ? eb2 : cb2) + it * CDIM;
    const float* Wwa  = (b ? eWwa : cWwa) + it * R * R;
    const float* bwa  = (b ? ebwa : cbwa) + it * R;
    const float* wtab = b ? wD : wC;
    int tid = threadIdx.x;  // 256 threads

    if (tid < NF * CDIM) sL[tid] = d_l_cur[b][tid];
    __syncthreads();

    {
        int f = tid >> 6, j = tid & 63;
        float s1 = b1[j], s2 = b2[j];
#pragma unroll 8
        for (int k = 0; k < CDIM; k++) {
            float lv = sL[f * CDIM + k];
            s1 = fmaf(lv, W1[k * CDIM + j], s1);
            s2 = fmaf(lv, W2[k * CDIM + j], s2);
        }
        d_L1[b][tid] = s1;
        sLW2[tid] = s2;
    }
    for (int o = tid; o < R * CDIM; o += 256) {
        int r = o >> 6, j = o & 63;
        float s = b2[j];
#pragma unroll 8
        for (int k = 0; k < CDIM; k++) s = fmaf(wtab[r * CDIM + k], W2[k * CDIM + j], s);
        sWW2[o] = s;
    }
    __syncthreads();

    for (int o = tid; o < NF * R; o += 256) {
        int f = o / R, r = o % R;
        float s = 0.f;
#pragma unroll 8
        for (int jx = 0; jx < CDIM; jx++) s = fmaf(sLW2[f * CDIM + jx], sWW2[r * CDIM + jx], s);
        srp[o] = s;
    }
    __syncthreads();

    for (int o = tid; o < NF * R; o += 256) {
        int f = o / R, r2 = o % R;
        float s = bwa[r2];
        for (int r = 0; r < R; r++) s = fmaf(srp[f * R + r], Wwa[r * R + r2], s);
        sact[o] = (s >= 0.f) ? s : 0.2f * s;
    }
    __syncthreads();

    if (tid < NF) {
        float m = -1e30f;
        for (int r = 0; r < R; r++) m = fmaxf(m, sact[tid * R + r]);
        float sum = 0.f;
        for (int r = 0; r < R; r++) { float ev = expf(sact[tid * R + r] - m); sact[tid * R + r] = ev; sum += ev; }
        float inv = 1.f / sum;
        for (int r = 0; r < R; r++) sact[tid * R + r] *= inv;
    }
    __syncthreads();

    float lnew;
    {
        int f = tid >> 6, j = tid & 63;
        float s = 0.f;
        for (int r = 0; r < R; r++) s = fmaf(sact[f * R + r], wtab[r * CDIM + j], s);
        d_l_new[b][tid] = s;
        lnew = s;
    }

    // ---- fused latent_post epilogue ----
    float ps = warp_sum(lnew * lnew);
    if ((tid & 31) == 0) wsum[tid >> 5] = ps;
    __syncthreads();
    int f = tid >> 6;
    float nrm = sqrtf(wsum[2 * f] + wsum[2 * f + 1]);
    float inv = 1.f / fmaxf(nrm, 1e-12f);
    float n = lnew * inv;
    if (b == 1) {
        d_l_cur[1][tid] = n;
        d_l_acc[1][tid] += n;
    } else {
        d_l_cur[0][tid] = lnew;
        if (is_last) d_l_acc[0][tid] = n + lnew;
    }
}

// ============ entity pass: it0 dual (fp16 staged input, packed store) ======
__global__ __launch_bounds__(256) void ent_pass_dual(
    const float* __restrict__ wC, const float* __restrict__ wD,
    const float* __restrict__ ent_emb,
    float* __restrict__ outC, float* __restrict__ outD) {
    __shared__ float2 swC[R1 * 32];
    __shared__ float2 swD[R2 * 32];
    int tid = threadIdx.x;
    for (int o = tid; o < R1 * 32; o += 256) swC[o] = ((const float2*)wC)[o];
    for (int o = tid; o < R2 * 32; o += 256) swD[o] = ((const float2*)wD)[o];
    __syncthreads();
    int warp = tid >> 5, lane = tid & 31;
    int h = blockIdx.x * 8 + warp;
    if (h >= N_ENT) return;
    int s = d_start[h], e = d_start[h + 1];
    float cx = 0.f, cy = 0.f, dx = 0.f, dy = 0.f;
#pragma unroll 4
    for (int k = s; k < e; k++) {
        int p = __ldg(&d_pack[k]);
        int t = p & 0x1FFFF;
        float2 ev = __half22float2(d_ein16[t * 32 + lane]);
        float2 wc = swC[((p >> 17) & 15) * 32 + lane];
        float2 wd = swD[((p >> 21) & 63) * 32 + lane];
        cx = fmaf(ev.x, wc.x, cx); cy = fmaf(ev.y, wc.y, cy);
        dx = fmaf(ev.x, wd.x, dx); dy = fmaf(ev.y, wd.y, dy);
    }
    float ic = 1.f / fmaxf((float)(e - s), 1.f);
    cx *= ic; cy *= ic; dx *= ic; dy *= ic;
    float sC = warp_sum(cx * cx + cy * cy);
    float sD = warp_sum(dx * dx + dy * dy);
    float iC = 1.f / fmaxf(sqrtf(sC), 1e-12f);
    float iD = 1.f / fmaxf(sqrtf(sD), 1e-12f);
    cx *= iC; cy *= iC; dx *= iD; dy *= iD;
    CDPack pk;
    pk.h[0] = __floats2half2_rn(cx, cy);
    pk.h[1] = __floats2half2_rn(dx, dy);
    d_eCD[h * 32 + lane] = pk.f;
    float2 e2 = ((const float2*)ent_emb)[h * 32 + lane];
    ((float2*)outC)[h * 32 + lane] = make_float2(e2.x + cx, e2.y + cy);
    outD[h * 64 + 2 * lane]     = e2.x + dx;
    outD[h * 64 + 2 * lane + 1] = e2.y + dy;
}

// ====== entity pass: it1 both branches fused (packed fp16 state) ===========
__global__ __launch_bounds__(256) void ent_pass_final(
    const float* __restrict__ wC, const float* __restrict__ wD,
    float* __restrict__ outC, float* __restrict__ outD) {
    __shared__ float2 swC[R1 * 32];
    __shared__ float2 swD[R2 * 32];
    int tid = threadIdx.x;
    for (int o = tid; o < R1 * 32; o += 256) swC[o] = ((const float2*)wC)[o];
    for (int o = tid; o < R2 * 32; o += 256) swD[o] = ((const float2*)wD)[o];
    __syncthreads();
    int warp = tid >> 5, lane = tid & 31;
    int h = blockIdx.x * 8 + warp;
    if (h >= N_ENT) return;
    int s = d_start[h], e = d_start[h + 1];
    float cx = 0.f, cy = 0.f, dx = 0.f, dy = 0.f;
#pragma unroll 4
    for (int k = s; k < e; k++) {
        int p = __ldg(&d_pack[k]);
        int t = p & 0x1FFFF;
        CDPack pk;
        pk.f = __ldg(&d_eCD[t * 32 + lane]);
        float2 evC = __half22float2(pk.h[0]);
        float2 evD = __half22float2(pk.h[1]);
        float2 wc = swC[((p >> 17) & 15) * 32 + lane];
        float2 wd = swD[((p >> 21) & 63) * 32 + lane];
        cx = fmaf(evC.x, wc.x, cx); cy = fmaf(evC.y, wc.y, cy);
        dx = fmaf(evD.x, wd.x, dx); dy = fmaf(evD.y, wd.y, dy);
    }
    float ic = 1.f / fmaxf((float)(e - s), 1.f);
    cx *= ic; cy *= ic; dx *= ic; dy *= ic;
    float sC = warp_sum(cx * cx + cy * cy);
    float sD = warp_sum(dx * dx + dy * dy);
    float iC = 1.f / fmaxf(sqrtf(sC), 1e-12f);
    float iD = 1.f / fmaxf(sqrtf(sD), 1e-12f);
    cx *= iC; cy *= iC; dx *= iD; dy *= iD;
    float2 o2 = ((const float2*)outC)[h * 32 + lane];
    ((float2*)outC)[h * 32 + lane] = make_float2(o2.x + cx, o2.y + cy);
    outD[h * 64 + 2 * lane]     += dx;
    outD[h * 64 + 2 * lane + 1] += dy;
}

// ================= user score/mix epilogues =================================
struct UsrShared {
    float W1[4096];
    float b1[64], L1[256], LN[256], Wua[16], bua[4];
    float Row[8][64];
};

__device__ __forceinline__ void usr_epi_core(
    const UsrShared& sh, int lane, float a0, float a1,
    float ax, float ay, float& rx, float& ry) {
    float sc0 = warp_sum(a0 * sh.L1[lane] + a1 * sh.L1[lane + 32]);
    float sc1 = warp_sum(a0 * sh.L1[64 + lane] + a1 * sh.L1[64 + lane + 32]);
    float sc2 = warp_sum(a0 * sh.L1[128 + lane] + a1 * sh.L1[128 + lane + 32]);
    float sc3 = warp_sum(a0 * sh.L1[192 + lane] + a1 * sh.L1[192 + lane + 32]);
    float t[4]; float m = -1e30f;
#pragma unroll
    for (int g = 0; g < 4; g++) {
        float sv = sh.bua[g] + sc0 * sh.Wua[g] + sc1 * sh.Wua[4 + g]
                 + sc2 * sh.Wua[8 + g] + sc3 * sh.Wua[12 + g];
        sv = (sv >= 0.f) ? sv : 0.2f * sv;
        t[g] = sv; m = fmaxf(m, sv);
    }
    float es = 0.f;
#pragma unroll
    for (int g = 0; g < 4; g++) { t[g] = expf(t[g] - m); es += t[g]; }
    float ies = 1.f / es;
    float mixx = 0.f, mixy = 0.f;
#pragma unroll
    for (int g = 0; g < 4; g++) {
        float sg = t[g] * ies;
        mixx = fmaf(sg, sh.LN[g * 64 + 2 * lane], mixx);
        mixy = fmaf(sg, sh.LN[g * 64 + 2 * lane + 1], mixy);
    }
    rx = ax * (1.f + mixx); ry = ay * (1.f + mixy);
    float ss = warp_sum(rx * rx + ry * ry);
    float inv = 1.f / fmaxf(sqrtf(ss), 1e-12f);
    rx *= inv; ry *= inv;
}

__device__ __forceinline__ void usr_load_shared(
    UsrShared& sh, int tid, int b,
    const float* W1, const float* b1, const float* Wua, const float* bua) {
    for (int o = tid; o < 4096; o += 256) sh.W1[o] = W1[o];
    if (tid < 64) sh.b1[tid] = b1[tid];
    if (tid < 256) { sh.L1[tid] = d_L1[b][tid]; sh.LN[tid] = d_l_new[b][tid]; }
    if (tid < 16) sh.Wua[tid] = Wua[tid];
    if (tid < 4) sh.bua[tid] = bua[tid];
}

// ====== user pass: it0 dual (fp16 staged input, merged dual epilogue) ======
__global__ __launch_bounds__(256) void usr_pass_dual(
    const float* __restrict__ u_emb,
    const float* __restrict__ W1a, const float* __restrict__ b1a,
    const float* __restrict__ Wua_a, const float* __restrict__ bua_a,
    const float* __restrict__ W1b, const float* __restrict__ b1b,
    const float* __restrict__ Wua_b, const float* __restrict__ bua_b,
    float* __restrict__ outA, float* __restrict__ outB) {
    __shared__ UsrShared shA;
    __shared__ UsrShared shB;
    int tid = threadIdx.x;
    usr_load_shared(shA, tid, 0, W1a, b1a, Wua_a, bua_a);
    usr_load_shared(shB, tid, 1, W1b, b1b, Wua_b, bua_b);
    __syncthreads();
    int warp = tid >> 5, lane = tid & 31;
    int u = blockIdx.x * 8 + warp;
    if (u >= N_USERS) return;
    int s = d_ustart[u], e = d_ustart[u + 1];
    float ax = 0.f, ay = 0.f;
#pragma unroll 4
    for (int k = s; k < e; k++) {
        int2 nz = __ldg(&d_unnz[k]);
        float v = __int_as_float(nz.y);
        float2 ev = __half22float2(d_ein16[nz.x * 32 + lane]);
        ax = fmaf(ev.x, v, ax); ay = fmaf(ev.y, v, ay);
    }
    float2 u2 = ((const float2*)u_emb)[u * 32 + lane];
    // single Row write, one k-loop feeding BOTH branches' W1 matvecs
    shA.Row[warp][2 * lane] = u2.x; shA.Row[warp][2 * lane + 1] = u2.y;
    __syncwarp();
    float a0A = shA.b1[lane], a1A = shA.b1[lane + 32];
    float a0B = shB.b1[lane], a1B = shB.b1[lane + 32];
#pragma unroll 16
    for (int k = 0; k < 64; k++) {
        float uk = shA.Row[warp][k];
        a0A = fmaf(uk, shA.W1[k * 64 + lane], a0A);
        a1A = fmaf(uk, shA.W1[k * 64 + lane + 32], a1A);
        a0B = fmaf(uk, shB.W1[k * 64 + lane], a0B);
        a1B = fmaf(uk, shB.W1[k * 64 + lane + 32], a1B);
    }
    float rxA, ryA, rxB, ryB;
    usr_epi_core(shA, lane, a0A, a1A, ax, ay, rxA, ryA);
    usr_epi_core(shB, lane, a0B, a1B, ax, ay, rxB, ryB);
    CDPack pk;
    pk.h[0] = __floats2half2_rn(rxA, ryA);
    pk.h[1] = __floats2half2_rn(rxB, ryB);
    d_uCD[u * 32 + lane] = pk.f;
    ((float2*)outA)[u * 32 + lane] = make_float2(u2.x + rxA, u2.y + ryA);
    outB[u * 64 + 2 * lane]     = u2.x + rxB;
    outB[u * 64 + 2 * lane + 1] = u2.y + ryB;
}

// ====== user pass: it1 both branches fused (merged dual epilogue) ==========
__global__ __launch_bounds__(256) void usr_pass_final(
    const float* __restrict__ W1a, const float* __restrict__ b1a,
    const float* __restrict__ Wua_a, const float* __restrict__ bua_a,
    const float* __restrict__ W1b, const float* __restrict__ b1b,
    const float* __restrict__ Wua_b, const float* __restrict__ bua_b,
    float* __restrict__ outA, float* __restrict__ outB) {
    __shared__ UsrShared shA;
    __shared__ UsrShared shB;
    int tid = threadIdx.x;
    usr_load_shared(shA, tid, 0, W1a, b1a, Wua_a, bua_a);
    usr_load_shared(shB, tid, 1, W1b, b1b, Wua_b, bua_b);
    __syncthreads();
    int warp = tid >> 5, lane = tid & 31;
    int u = blockIdx.x * 8 + warp;
    if (u >= N_USERS) return;
    int s = d_ustart[u], e = d_ustart[u + 1];
    float axA = 0.f, ayA = 0.f, axB = 0.f, ayB = 0.f;
#pragma unroll 4
    for (int k = s; k < e; k++) {
        int2 nz = __ldg(&d_unnz[k]);
        float v = __int_as_float(nz.y);
        CDPack pk;
        pk.f = __ldg(&d_eCD[nz.x * 32 + lane]);
        float2 evA = __half22float2(pk.h[0]);
        float2 evB = __half22float2(pk.h[1]);
        axA = fmaf(evA.x, v, axA); ayA = fmaf(evA.y, v, ayA);
        axB = fmaf(evB.x, v, axB); ayB = fmaf(evB.y, v, ayB);
    }
    CDPack ur;
    ur.f = d_uCD[u * 32 + lane];
    float2 uA = __half22float2(ur.h[0]);
    float2 uB = __half22float2(ur.h[1]);
    // stage both rows, one k-loop for both branches' W1 matvecs
    shA.Row[warp][2 * lane] = uA.x; shA.Row[warp][2 * lane + 1] = uA.y;
    shB.Row[warp][2 * lane] = uB.x; shB.Row[warp][2 * lane + 1] = uB.y;
    __syncwarp();
    float a0A = shA.b1[lane], a1A = shA.b1[lane + 32];
    float a0B = shB.b1[lane], a1B = shB.b1[lane + 32];
#pragma unroll 16
    for (int k = 0; k < 64; k++) {
        float ukA = shA.Row[warp][k];
        float ukB = shB.Row[warp][k];
        a0A = fmaf(ukA, shA.W1[k * 64 + lane], a0A);
        a1A = fmaf(ukA, shA.W1[k * 64 + lane + 32], a1A);
        a0B = fmaf(ukB, shB.W1[k * 64 + lane], a0B);
        a1B = fmaf(ukB, shB.W1[k * 64 + lane + 32], a1B);
    }
    float rx, ry;
    usr_epi_core(shA, lane, a0A, a1A, axA, ayA, rx, ry);
    {
        float2 o2 = ((const float2*)outA)[u * 32 + lane];
        ((float2*)outA)[u * 32 + lane] = make_float2(o2.x + rx, o2.y + ry);
    }
    usr_epi_core(shB, lane, a0B, a1B, axB, ayB, rx, ry);
    outB[u * 64 + 2 * lane]     += rx;
    outB[u * 64 + 2 * lane + 1] += ry;
}

// ========= distance-correlation: 12 blocks (6 pairs x 2 branches) ==========
__global__ void cor_kernel(float* __restrict__ out0, float* __restrict__ out1) {
    __shared__ float t1[64], t2[64];
    __shared__ float Ma[4096], Mb[4096];
    __shared__ float cmA[64], rmA[64], cmB[64], rmB[64];
    __shared__ float gA, gB;
    __shared__ float r0[256], r1[256], r2[256];
    int tid = threadIdx.x;
    const int PI[6] = {0, 0, 0, 1, 1, 2};
    const int PJ[6] = {1, 2, 3, 2, 3, 3};
    int b = blockIdx.x / 6;
    int pr = blockIdx.x % 6;
    float* out = b ? out1 : out0;
    int i = PI[pr], j = PJ[pr];
    if (tid < 64) { t1[tid] = d_l_acc[b][i * 64 + tid]; t2[tid] = d_l_acc[b][j * 64 + tid]; }
    __syncthreads();
    for (int o = tid; o < 4096; o += 256) {
        int p = o >> 6, q = o & 63;
        float va = t1[p] * t1[p] - 2.f * t1[p] * t1[q] + t1[q] * t1[q];
        float vb = t2[p] * t2[p] - 2.f * t2[p] * t2[q] + t2[q] * t2[q];
        Ma[o] = sqrtf(fmaxf(va, 0.f) + 1e-8f);
        Mb[o] = sqrtf(fmaxf(vb, 0.f) + 1e-8f);
    }
    __syncthreads();
    if (tid < 64) {
        float s = 0.f;
        for (int p = 0; p < 64; p++) s += Ma[p * 64 + tid];
        cmA[tid] = s * (1.f / 64.f);
    } else if (tid < 128) {
        int p = tid - 64; float s = 0.f;
        for (int q = 0; q < 64; q++) s += Ma[p * 64 + q];
        rmA[p] = s * (1.f / 64.f);
    } else if (tid < 192) {
        int q = tid - 128; float s = 0.f;
        for (int p = 0; p < 64; p++) s += Mb[p * 64 + q];
        cmB[q] = s * (1.f / 64.f);
    } else {
        int p = tid - 192; float s = 0.f;
        for (int q = 0; q < 64; q++) s += Mb[p * 64 + q];
        rmB[p] = s * (1.f / 64.f);
    }
    __syncthreads();
    if (tid == 0) { float s = 0.f; for (int q = 0; q < 64; q++) s += cmA[q]; gA = s * (1.f / 64.f); }
    if (tid == 1) { float s = 0.f; for (int q = 0; q < 64; q++) s += cmB[q]; gB = s * (1.f / 64.f); }
    __syncthreads();
    float ab = 0.f, aa = 0.f, bb = 0.f;
    for (int o = tid; o < 4096; o += 256) {
        int p = o >> 6, q = o & 63;
        float Ac = Ma[o] - cmA[q] - rmA[p] + gA;
        float Bc = Mb[o] - cmB[q] - rmB[p] + gB;
        ab = fmaf(Ac, Bc, ab); aa = fmaf(Ac, Ac, aa); bb = fmaf(Bc, Bc, bb);
    }
    r0[tid] = ab; r1[tid] = aa; r2[tid] = bb;
    __syncthreads();
    for (int s = 128; s; s >>= 1) {
        if (tid < s) { r0[tid] += r0[tid + s]; r1[tid] += r1[tid + s]; r2[tid] += r2[tid + s]; }
        __syncthreads();
    }
    if (tid == 0) {
        const float n2 = 4096.f;
        float dab = sqrtf(fmaxf(r0[0] / n2, 0.f) + 1e-8f);
        float daa = sqrtf(fmaxf(r1[0] / n2, 0.f) + 1e-8f);
        float dbb = sqrtf(fmaxf(r2[0] / n2, 0.f) + 1e-8f);
        atomicAdd(out, dab / sqrtf(daa * dbb + 1e-8f));
    }
}

// ================= host =================
extern "C" void kernel_launch(void* const* d_in, const int* in_sizes, int n_in,
                              void* d_out, int out_size) {
    const float* user_emb       = (const float*)d_in[0];
    const float* entity_emb     = (const float*)d_in[1];
    const float* latent_emb     = (const float*)d_in[2];
    const float* latent_div_emb = (const float*)d_in[3];
    const float* weight         = (const float*)d_in[4];
    const float* weight_d       = (const float*)d_in[5];
    const float* cW1  = (const float*)d_in[6];
    const float* cb1  = (const float*)d_in[7];
    const float* cW2  = (const float*)d_in[8];
    const float* cb2  = (const float*)d_in[9];
    const float* cWua = (const float*)d_in[10];
    const float* cbua = (const float*)d_in[11];
    const float* cWwa = (const float*)d_in[12];
    const float* cbwa = (const float*)d_in[13];
    const float* eW1  = (const float*)d_in[14];
    const float* eb1  = (const float*)d_in[15];
    const float* eW2  = (const float*)d_in[16];
    const float* eb2  = (const float*)d_in[17];
    const float* eWua = (const float*)d_in[18];
    const float* ebua = (const float*)d_in[19];
    const float* eWwa = (const float*)d_in[20];
    const float* ebwa = (const float*)d_in[21];
    const float* interact_vals = (const float*)d_in[22];
    const int*   edge_index    = (const int*)d_in[23];
    const int*   edge_type     = (const int*)d_in[24];
    const int*   cate          = (const int*)d_in[25];
    const int*   irows         = (const int*)d_in[26];
    const int*   icols         = (const int*)d_in[27];

    const int* head = edge_index;
    const int* tail = edge_index + E_EDGES;
    float* out = (float*)d_out;

    const int ENT_BLOCKS = (N_ENT + 7) / 8;     // 12500
    const int USR_BLOCKS = (N_USERS + 7) / 8;   // 6250

    // ---- CSR build + fp16 input staging ----
    setup_kernel<<<512, 256>>>(out + OUT_COR0, out + OUT_COR1,
                               latent_emb, latent_div_emb,
                               (const float2*)entity_emb);
    cnt_all<<<(E_EDGES + 255) / 256, 256>>>(head, irows);
    scan_phaseA<<<EBLK + UBLK, 256>>>();
    scan_phaseC<<<EBLK + UBLK, 256>>>();
    fill_all<<<(E_EDGES + 255) / 256, 256>>>(head, tail, edge_type, cate,
                                             irows, icols, interact_vals);

    // ---- iteration 0 (both branches fused; fp16 staged input) ----
    dense_both<<<2, 256>>>(cW1, cb1, cW2, cb2, cWwa, cbwa, weight,
                           eW1, eb1, eW2, eb2, eWwa, ebwa, weight_d, 0, 0);
    ent_pass_dual<<<ENT_BLOCKS, 256>>>(weight, weight_d, entity_emb,
                                       out + OUT_E0, out + OUT_E1);
    usr_pass_dual<<<USR_BLOCKS, 256>>>(user_emb,
                                       cW1, cb1, cWua, cbua,
                                       eW1, eb1, eWua, ebua,
                                       out + OUT_U0, out + OUT_U1);

    // ---- iteration 1 (both branches fused; out += only; fp16 state) ----
    dense_both<<<2, 256>>>(cW1, cb1, cW2, cb2, cWwa, cbwa, weight,
                           eW1, eb1, eW2, eb2, eWwa, ebwa, weight_d, 1, 1);
    ent_pass_final<<<ENT_BLOCKS, 256>>>(weight, weight_d, out + OUT_E0, out + OUT_E1);
    usr_pass_final<<<USR_BLOCKS, 256>>>(cW1 + 4096, cb1 + 64, cWua + 16, cbua + 4,
                                        eW1 + 4096, eb1 + 64, eWua + 16, ebua + 4,
                                        out + OUT_U0, out + OUT_U1);

    // ---- distance correlations (both branches, one launch) ----
    cor_kernel<<<12, 256>>>(out + OUT_COR0, out + OUT_COR1);
}